// round 4
// baseline (speedup 1.0000x reference)
#include <cuda_runtime.h>

#define HH 1536
#define WW 2048
#define QPR (WW / 4)          // float4 quads per row = 512
#define PLANE (HH * WW)

__global__ __launch_bounds__(256)
void count_stencil_kernel(const float* __restrict__ in,
                          const int* __restrict__ stride_p,
                          float* __restrict__ out) {
    int q = blockIdx.x * blockDim.x + threadIdx.x;   // quad index within row
    int h = blockIdx.y;
    if (q >= QPR) return;
    int c = q << 2;                                  // leftmost pixel column of this quad
    float s = (float)(*stride_p);

    // Load 3 rows x 6 columns (c-1 .. c+4), relu'd, zero-padded at borders.
    float row[3][6];
    const float4* in4 = (const float4*)in;
#pragma unroll
    for (int dr = 0; dr < 3; dr++) {
        int r = h + dr - 1;
        if (r < 0 || r >= HH) {
#pragma unroll
            for (int i = 0; i < 6; i++) row[dr][i] = 0.f;
        } else {
            float4 v = __ldg(&in4[r * QPR + q]);
            row[dr][1] = fmaxf(v.x, 0.f);
            row[dr][2] = fmaxf(v.y, 0.f);
            row[dr][3] = fmaxf(v.z, 0.f);
            row[dr][4] = fmaxf(v.w, 0.f);
            row[dr][0] = (c > 0)      ? fmaxf(__ldg(&in[r * WW + c - 1]), 0.f) : 0.f;
            row[dr][5] = (c + 4 < WW) ? fmaxf(__ldg(&in[r * WW + c + 4]), 0.f) : 0.f;
        }
    }

    float fo[4], wo[4], ho[4];
#pragma unroll
    for (int p = 0; p < 4; p++) {
        // taps in unfold order (kh, kw): 0..8, center = 4
        float t0 = row[0][p], t1 = row[0][p + 1], t2 = row[0][p + 2];
        float t3 = row[1][p], t4 = row[1][p + 1], t5 = row[1][p + 2];
        float t6 = row[2][p], t7 = row[2][p + 1], t8 = row[2][p + 2];

        float cnt = t0 + t1 + t2 + t3 + t4 + t5 + t6 + t7 + t8;

        // argmax == center (first-occurrence tie-break): strictly greater than
        // earlier taps, >= later taps.
        bool mask = (t4 > t0) & (t4 > t1) & (t4 > t2) & (t4 > t3)
                  & (t4 >= t5) & (t4 >= t6) & (t4 >= t7) & (t4 >= t8);
        float filt = ((cnt > 0.5f) && mask) ? 1.f : 0.f;

        float inv = 1.f / fmaxf(cnt, 1e-12f);

        // centroid: factor into row-sums (for h coord) and col-sums (for w coord).
        // Padded taps have value 0 => weight 0, so using the unclamped coordinate
        // at padded positions is exact.
        float r0s = t0 + t1 + t2, r1s = t3 + t4 + t5, r2s = t6 + t7 + t8;
        float c0s = t0 + t3 + t6, c1s = t1 + t4 + t7, c2s = t2 + t5 + t8;

        float fh = ((float)(h - 1) * r0s + (float)h * r1s + (float)(h + 1) * r2s) * inv;
        float wc = (float)(c + p);
        float fw = ((wc - 1.f) * c0s + wc * c1s + (wc + 1.f) * c2s) * inv;

        fo[p] = filt;
        wo[p] = s * fw + 0.5f;
        ho[p] = s * fh + 0.5f;
    }

    float4* out4 = (float4*)out;
    int base = h * QPR + q;
    out4[base]                = make_float4(fo[0], fo[1], fo[2], fo[3]);
    out4[(PLANE / 4) + base]     = make_float4(wo[0], wo[1], wo[2], wo[3]);
    out4[2 * (PLANE / 4) + base] = make_float4(ho[0], ho[1], ho[2], ho[3]);
}

extern "C" void kernel_launch(void* const* d_in, const int* in_sizes, int n_in,
                              void* d_out, int out_size) {
    const float* in = (const float*)d_in[0];
    const int* stride_p = (const int*)d_in[2];   // inputs: map, loc_kernel_size, stride
    float* out = (float*)d_out;

    dim3 block(256, 1, 1);
    dim3 grid((QPR + 255) / 256, HH, 1);
    count_stencil_kernel<<<grid, block>>>(in, stride_p, out);
}